// round 14
// baseline (speedup 1.0000x reference)
#include <cuda_runtime.h>

__device__ double g_rot_acc[64];
__device__ double g_str_acc[64];
__device__ unsigned int g_ticket = 0;

#define TPB 128
#define PPT 8
#define NH (PPT + 2)   // 10 hinges per thread: h = s-2 .. s+7
#define NE (PPT + 3)   // 11 edge vectors: vec j = edge (s-2+j)
#define WAVE_CTAS 912  // 152 SMs * 6 CTAs resident

__device__ __forceinline__ void pf_l2(const void* p) {
    asm volatile("prefetch.global.L2 [%0];" :: "l"(p));
}

// Full branch-free atan2 (cephes core), abs err ~1e-7 rad. Fallback path.
__device__ __noinline__ float full_atan2f(float y, float x) {
    float ay = fabsf(y), ax = fabsf(x);
    float mn = fminf(ay, ax), mx = fmaxf(ay, ax);
    bool  big = mn > 0.41421356237f * mx;
    float num = big ? (mn - mx) : mn;
    float den = big ? (mn + mx) : mx;
    float z = __fdividef(num, den);
    float s = z * z;
    float p = fmaf(fmaf(fmaf(fmaf(8.05374449538e-2f, s, -1.38776856032e-1f), s,
                             1.99777106478e-1f), s, -3.33329491539e-1f),
                   s * z, z);
    float r = big ? (0.78539816339744831f + p) : p;
    if (ay > ax) r = 1.57079632679489662f - r;
    if (x < 0.0f) r = 3.14159265358979323f - r;
    return copysignf(r, y);
}

// atan2 specialized for |y| <= 0.414*x (true for this data: edge ~ (1, +-0.03)).
__device__ __forceinline__ float edge_atan2f(float y, float x) {
    if (__builtin_expect(fabsf(y) <= 0.41421356237f * x, 1)) {
        float z = __fdividef(y, x);
        float s = z * z;
        return fmaf(fmaf(fmaf(fmaf(8.05374449538e-2f, s, -1.38776856032e-1f), s,
                              1.99777106478e-1f), s, -3.33329491539e-1f),
                    s * z, z);
    }
    return full_atan2f(y, x);
}

__global__ void __launch_bounds__(TPB, 6)
chain_kernel(const float2* __restrict__ pos,
             const float*  __restrict__ th_ss,
             const float*  __restrict__ rest,
             const float*  __restrict__ p_kstiff,
             const float*  __restrict__ p_ksoft,
             const float*  __restrict__ p_kstretch,
             const int2*   __restrict__ buckle,
             float*        __restrict__ out,
             int H, unsigned totalWarps)
{
    const int N = H + 2;
    const int t = blockIdx.x * TPB + threadIdx.x;
    const int s = t * PPT;

    // ---- cross-wave L2 prefetch: warm data for block (bid + WAVE_CTAS) ----
    {
        const int s_pf = s + WAVE_CTAS * TPB * PPT;
        if (s_pf + PPT <= H && s_pf >= PPT) {
            pf_l2((const char*)(pos + (s_pf - 2)));        // 96B region:
            pf_l2((const char*)(pos + (s_pf - 2)) + 64);   //   2 lines
            pf_l2((const char*)(th_ss + (s_pf - 2)));      // 40B: 1 line
            pf_l2((const char*)(buckle + (s_pf - 2)));     // 80B region:
            pf_l2((const char*)(buckle + (s_pf - 2)) + 64);//   2 lines
            pf_l2((const char*)(rest + (s_pf - 1)));       // 44B: 1 line
        }
    }

    const float k_stiff   = __ldg(p_kstiff);
    const float k_soft    = __ldg(p_ksoft);
    const float k_stretch = __ldg(p_kstretch);

    float rot_e = 0.f, str_e = 0.f;   // raw sums: keff*diff^2 and dl^2

    const bool fast = (s >= PPT) && (s + PPT <= H);

    if (s < N) {
        float Ex[NE], Ey[NE];
        float TH[NH], B0[NH], B1[NH];
        float RL[NE];                  // RL[1..9] real; 0,10 dummies

        // ================= loads (only part that branches) =================
        if (fast) {
            {
                float px[PPT + 4], py[PPT + 4];
                const float4* p4 = (const float4*)(pos + (s - 2));
                #pragma unroll
                for (int i = 0; i < 6; i++) {
                    float4 v = __ldg(&p4[i]);
                    px[2 * i] = v.x; py[2 * i] = v.y;
                    px[2 * i + 1] = v.z; py[2 * i + 1] = v.w;
                }
                #pragma unroll
                for (int j = 0; j < NE; j++) {
                    Ex[j] = px[j + 1] - px[j];
                    Ey[j] = py[j + 1] - py[j];
                }
            }
            {
                float2 c2 = __ldg((const float2*)(th_ss + (s - 2)));
                TH[0] = c2.x; TH[1] = c2.y;
                float4 a = __ldg((const float4*)(th_ss + s));
                float4 b = __ldg((const float4*)(th_ss + s + 4));
                TH[2] = a.x; TH[3] = a.y; TH[4] = a.z; TH[5] = a.w;
                TH[6] = b.x; TH[7] = b.y; TH[8] = b.z; TH[9] = b.w;
            }
            {
                const int4* b4 = (const int4*)(buckle + (s - 2));
                #pragma unroll
                for (int i = 0; i < 5; i++) {
                    int4 v = __ldg(&b4[i]);
                    B0[2 * i]     = (float)v.x; B1[2 * i]     = (float)v.y;
                    B0[2 * i + 1] = (float)v.z; B1[2 * i + 1] = (float)v.w;
                }
            }
            {
                RL[0] = 1.f;
                RL[1] = __ldg(&rest[s - 1]);
                float4 a = __ldg((const float4*)(rest + s));
                float4 b = __ldg((const float4*)(rest + s + 4));
                RL[2] = a.x; RL[3] = a.y; RL[4] = a.z; RL[5] = a.w;
                RL[6] = b.x; RL[7] = b.y; RL[8] = b.z; RL[9] = b.w;
                RL[10] = 1.f;
            }
        } else {
            {
                float px[PPT + 4], py[PPT + 4];
                #pragma unroll
                for (int j = 0; j < PPT + 4; j++) {
                    int g = max(0, min(s - 2 + j, N - 1));
                    float2 v = __ldg(&pos[g]);
                    px[j] = v.x; py[j] = v.y;
                }
                #pragma unroll
                for (int j = 0; j < NE; j++) {
                    int e = s - 2 + j;
                    bool ve = (e >= 0) && (e <= H);
                    Ex[j] = ve ? (px[j + 1] - px[j]) : 1.f;  // dummy (1,0): phi=0, len=1
                    Ey[j] = ve ? (py[j + 1] - py[j]) : 0.f;
                }
            }
            #pragma unroll
            for (int i = 0; i < NH; i++) {
                int h = s - 2 + i;
                bool v = (h >= 0) && (h < H);
                TH[i] = v ? __ldg(&th_ss[h]) : 0.f;
                int2 b = v ? __ldg(&buckle[h]) : make_int2(0, 0);
                B0[i] = (float)b.x; B1[i] = (float)b.y;
            }
            #pragma unroll
            for (int j = 0; j < NE; j++) {
                int e = s - 2 + j;
                RL[j] = ((e >= 0) && (e <= H)) ? __ldg(&rest[e]) : 1.f; // dummy -> dl=0
            }
        }

        // ============ pass A: per-edge absolute angles (11 indep chains) ============
        float phi[NE];
        #pragma unroll
        for (int m = 0; m < NE; m++)
            phi[m] = edge_atan2f(Ey[m], Ex[m]);

        // ============ pass B: hinges -> g, then c_m = g_{m-1} - g_m ============
        float c[NE - 1];   // c[1..9] used
        float gprev = 0.f;
        #pragma unroll
        for (int i = 0; i < NH; i++) {
            float theta = phi[i + 1] - phi[i];
            float th = TH[i];
            bool m0 = fmaf(theta, B0[i], th) > 0.f;
            bool m1 = fmaf(theta, B1[i], th) > 0.f;
            float keff = (m0 ? k_stiff : k_soft) + (m1 ? k_stiff : k_soft);
            float diff = theta - th;
            float g = keff * diff;
            bool vh = fast || (((s - 2 + i) >= 0) && ((s - 2 + i) < H));
            g = vh ? g : 0.f;
            if (i >= 2) rot_e = fmaf(g, diff, rot_e);    // raw keff*diff^2
            if (i >= 1 && i <= 9) c[i] = gprev - g;
            gprev = g;
        }

        // ============ pass C: combined edge force F_m, scatter to points ============
        // F_m = c_m * perp(E_m)/len^2 + k_str*dl*E_m/len ; G[j] = F_{j+1} - F_{j+2}
        float Gx[PPT], Gy[PPT];
        #pragma unroll
        for (int j = 0; j < PPT; j++) { Gx[j] = 0.f; Gy[j] = 0.f; }

        #pragma unroll
        for (int m = 1; m <= 9; m++) {
            float ex = Ex[m], ey = Ey[m];
            float lensq = fmaf(ex, ex, ey * ey);
            float rsq = rsqrtf(lensq);
            float len = lensq * rsq;
            float dl  = len - RL[m];                     // 0 for dummy edges
            if (m >= 2) str_e = fmaf(dl, dl, str_e);     // raw dl^2
            float fsc = k_stretch * dl * rsq;
            float psc = c[m] * rsq * rsq;
            float Fx = fmaf(fsc, ex, -psc * ey);
            float Fy = fmaf(fsc, ey,  psc * ex);
            if (m <= 8) { Gx[m - 1] += Fx; Gy[m - 1] += Fy; }   // j = m-1 (F_{j+1})
            if (m >= 2) { Gx[m - 2] -= Fx; Gy[m - 2] -= Fy; }   // j = m-2 (F_{j+2})
        }

        // ================= force writes (force = -G) =================
        if (fast) {
            out[3 + 2 * s] = -Gx[0];
            float4* o4 = (float4*)(out + 4 + 2 * s);
            o4[0] = make_float4(-Gy[0], -Gx[1], -Gy[1], -Gx[2]);
            o4[1] = make_float4(-Gy[2], -Gx[3], -Gy[3], -Gx[4]);
            o4[2] = make_float4(-Gy[4], -Gx[5], -Gy[5], -Gx[6]);
            out[16 + 2 * s] = -Gy[6];
            out[17 + 2 * s] = -Gx[7];
            out[18 + 2 * s] = -Gy[7];
        } else {
            #pragma unroll
            for (int j = 0; j < PPT; j++) {
                int p = s + j;
                if (p < N) {
                    bool z = (p < 2);
                    out[3 + 2 * p]     = z ? 0.f : -Gx[j];
                    out[3 + 2 * p + 1] = z ? 0.f : -Gy[j];
                }
            }
        }
    }

    // ---------------- energy reduction ----------------
    float r = rot_e, sv = str_e;
    #pragma unroll
    for (int off = 16; off > 0; off >>= 1) {
        r  += __shfl_down_sync(0xffffffffu, r,  off);
        sv += __shfl_down_sync(0xffffffffu, sv, off);
    }
    const int lane = threadIdx.x & 31;
    const int wid  = threadIdx.x >> 5;
    if (lane == 0) {
        int slot = (blockIdx.x * (TPB / 32) + wid) & 63;
        atomicAdd(&g_rot_acc[slot], 0.5 * (double)r);
        atomicAdd(&g_str_acc[slot], 0.5 * (double)k_stretch * (double)sv);
        __threadfence();
        unsigned tk = atomicAdd(&g_ticket, 1u);
        if (tk == totalWarps - 1u) {
            double R = 0.0, S = 0.0;
            #pragma unroll
            for (int i = 0; i < 64; i++) {
                R += g_rot_acc[i]; g_rot_acc[i] = 0.0;
                S += g_str_acc[i]; g_str_acc[i] = 0.0;
            }
            out[0] = (float)(R + S);
            out[1] = (float)R;
            out[2] = (float)S;
            g_ticket = 0u;
        }
    }
}

extern "C" void kernel_launch(void* const* d_in, const int* in_sizes, int n_in,
                              void* d_out, int out_size) {
    const float2* pos      = (const float2*)d_in[0];
    const float*  th_ss    = (const float*)d_in[1];
    const float*  rest     = (const float*)d_in[2];
    const float*  kstiff   = (const float*)d_in[3];
    const float*  ksoft    = (const float*)d_in[4];
    const float*  kstretch = (const float*)d_in[5];
    const int2*   buckle   = (const int2*)d_in[6];
    float* out = (float*)d_out;

    const int H = in_sizes[1];
    const int N = H + 2;
    const int threads_needed = (N + PPT - 1) / PPT;
    const int blocks = (threads_needed + TPB - 1) / TPB;
    const unsigned totalWarps = (unsigned)blocks * (TPB / 32);

    chain_kernel<<<blocks, TPB>>>(pos, th_ss, rest, kstiff, ksoft, kstretch,
                                  buckle, out, H, totalWarps);
}

// round 15
// speedup vs baseline: 1.4015x; 1.4015x over previous
#include <cuda_runtime.h>

__device__ double g_rot_acc[64];
__device__ double g_str_acc[64];
__device__ unsigned int g_ticket = 0;

#define TPB 128
#define PPT 8
#define NH (PPT + 2)   // 10 hinges per thread: h = s-2 .. s+7
#define NE (PPT + 3)   // 11 edge vectors: vec j = edge (s-2+j)

// Full branch-free atan2 (cephes core), abs err ~1e-7 rad. Fallback path.
__device__ __noinline__ float full_atan2f(float y, float x) {
    float ay = fabsf(y), ax = fabsf(x);
    float mn = fminf(ay, ax), mx = fmaxf(ay, ax);
    bool  big = mn > 0.41421356237f * mx;
    float num = big ? (mn - mx) : mn;
    float den = big ? (mn + mx) : mx;
    float z = __fdividef(num, den);
    float s = z * z;
    float p = fmaf(fmaf(fmaf(fmaf(8.05374449538e-2f, s, -1.38776856032e-1f), s,
                             1.99777106478e-1f), s, -3.33329491539e-1f),
                   s * z, z);
    float r = big ? (0.78539816339744831f + p) : p;
    if (ay > ax) r = 1.57079632679489662f - r;
    if (x < 0.0f) r = 3.14159265358979323f - r;
    return copysignf(r, y);
}

// atan2 specialized for |y| <= 0.414*x (true for this data: edge ~ (1, +-0.03)).
__device__ __forceinline__ float edge_atan2f(float y, float x) {
    if (__builtin_expect(fabsf(y) <= 0.41421356237f * x, 1)) {
        float z = __fdividef(y, x);
        float s = z * z;
        return fmaf(fmaf(fmaf(fmaf(8.05374449538e-2f, s, -1.38776856032e-1f), s,
                              1.99777106478e-1f), s, -3.33329491539e-1f),
                    s * z, z);
    }
    return full_atan2f(y, x);
}

__global__ void __launch_bounds__(TPB, 6)
chain_kernel(const float2* __restrict__ pos,
             const float*  __restrict__ th_ss,
             const float*  __restrict__ rest,
             const float*  __restrict__ p_kstiff,
             const float*  __restrict__ p_ksoft,
             const float*  __restrict__ p_kstretch,
             const int2*   __restrict__ buckle,
             float*        __restrict__ out,
             int H, unsigned totalWarps)
{
    const int N = H + 2;
    const int t = blockIdx.x * TPB + threadIdx.x;
    const int s = t * PPT;

    const float k_stiff   = __ldg(p_kstiff);
    const float k_soft    = __ldg(p_ksoft);
    const float k_stretch = __ldg(p_kstretch);

    float rot_e = 0.f, str_e = 0.f;   // raw sums: keff*diff^2 and dl^2

    const bool fast = (s >= PPT) && (s + PPT <= H);

    if (s < N) {
        float Ex[NE], Ey[NE];
        float TH[NH], B0[NH], B1[NH];
        float RL[NE];                  // RL[1..9] real; 0,10 dummies

        // ================= loads (only part that branches) =================
        if (fast) {
            {
                float px[PPT + 4], py[PPT + 4];
                const float4* p4 = (const float4*)(pos + (s - 2));
                #pragma unroll
                for (int i = 0; i < 6; i++) {
                    float4 v = __ldg(&p4[i]);
                    px[2 * i] = v.x; py[2 * i] = v.y;
                    px[2 * i + 1] = v.z; py[2 * i + 1] = v.w;
                }
                #pragma unroll
                for (int j = 0; j < NE; j++) {
                    Ex[j] = px[j + 1] - px[j];
                    Ey[j] = py[j + 1] - py[j];
                }
            }
            {
                float2 c2 = __ldg((const float2*)(th_ss + (s - 2)));
                TH[0] = c2.x; TH[1] = c2.y;
                float4 a = __ldg((const float4*)(th_ss + s));
                float4 b = __ldg((const float4*)(th_ss + s + 4));
                TH[2] = a.x; TH[3] = a.y; TH[4] = a.z; TH[5] = a.w;
                TH[6] = b.x; TH[7] = b.y; TH[8] = b.z; TH[9] = b.w;
            }
            {
                const int4* b4 = (const int4*)(buckle + (s - 2));
                #pragma unroll
                for (int i = 0; i < 5; i++) {
                    int4 v = __ldg(&b4[i]);
                    B0[2 * i]     = (float)v.x; B1[2 * i]     = (float)v.y;
                    B0[2 * i + 1] = (float)v.z; B1[2 * i + 1] = (float)v.w;
                }
            }
            {
                RL[0] = 1.f;
                RL[1] = __ldg(&rest[s - 1]);
                float4 a = __ldg((const float4*)(rest + s));
                float4 b = __ldg((const float4*)(rest + s + 4));
                RL[2] = a.x; RL[3] = a.y; RL[4] = a.z; RL[5] = a.w;
                RL[6] = b.x; RL[7] = b.y; RL[8] = b.z; RL[9] = b.w;
                RL[10] = 1.f;
            }
        } else {
            {
                float px[PPT + 4], py[PPT + 4];
                #pragma unroll
                for (int j = 0; j < PPT + 4; j++) {
                    int g = max(0, min(s - 2 + j, N - 1));
                    float2 v = __ldg(&pos[g]);
                    px[j] = v.x; py[j] = v.y;
                }
                #pragma unroll
                for (int j = 0; j < NE; j++) {
                    int e = s - 2 + j;
                    bool ve = (e >= 0) && (e <= H);
                    Ex[j] = ve ? (px[j + 1] - px[j]) : 1.f;  // dummy (1,0): phi=0, len=1
                    Ey[j] = ve ? (py[j + 1] - py[j]) : 0.f;
                }
            }
            #pragma unroll
            for (int i = 0; i < NH; i++) {
                int h = s - 2 + i;
                bool v = (h >= 0) && (h < H);
                TH[i] = v ? __ldg(&th_ss[h]) : 0.f;
                int2 b = v ? __ldg(&buckle[h]) : make_int2(0, 0);
                B0[i] = (float)b.x; B1[i] = (float)b.y;
            }
            #pragma unroll
            for (int j = 0; j < NE; j++) {
                int e = s - 2 + j;
                RL[j] = ((e >= 0) && (e <= H)) ? __ldg(&rest[e]) : 1.f; // dummy -> dl=0
            }
        }

        // ============ pass A: per-edge absolute angles (11 indep chains) ============
        float phi[NE];
        #pragma unroll
        for (int m = 0; m < NE; m++)
            phi[m] = edge_atan2f(Ey[m], Ex[m]);

        // ============ pass B: hinges -> g, then c_m = g_{m-1} - g_m ============
        float c[NE - 1];   // c[1..9] used
        float gprev = 0.f;
        #pragma unroll
        for (int i = 0; i < NH; i++) {
            float theta = phi[i + 1] - phi[i];
            float th = TH[i];
            bool m0 = fmaf(theta, B0[i], th) > 0.f;
            bool m1 = fmaf(theta, B1[i], th) > 0.f;
            float keff = (m0 ? k_stiff : k_soft) + (m1 ? k_stiff : k_soft);
            float diff = theta - th;
            float g = keff * diff;
            bool vh = fast || (((s - 2 + i) >= 0) && ((s - 2 + i) < H));
            g = vh ? g : 0.f;
            if (i >= 2) rot_e = fmaf(g, diff, rot_e);    // raw keff*diff^2
            if (i >= 1 && i <= 9) c[i] = gprev - g;
            gprev = g;
        }

        // ============ pass C: combined edge force F_m, scatter to points ============
        // F_m = c_m * perp(E_m)/len^2 + k_str*dl*E_m/len ; G[j] = F_{j+1} - F_{j+2}
        float Gx[PPT], Gy[PPT];
        #pragma unroll
        for (int j = 0; j < PPT; j++) { Gx[j] = 0.f; Gy[j] = 0.f; }

        #pragma unroll
        for (int m = 1; m <= 9; m++) {
            float ex = Ex[m], ey = Ey[m];
            float lensq = fmaf(ex, ex, ey * ey);
            float rsq = rsqrtf(lensq);
            float len = lensq * rsq;
            float dl  = len - RL[m];                     // 0 for dummy edges
            if (m >= 2) str_e = fmaf(dl, dl, str_e);     // raw dl^2
            float fsc = k_stretch * dl * rsq;
            float psc = c[m] * rsq * rsq;
            float Fx = fmaf(fsc, ex, -psc * ey);
            float Fy = fmaf(fsc, ey,  psc * ex);
            if (m <= 8) { Gx[m - 1] += Fx; Gy[m - 1] += Fy; }   // j = m-1 (F_{j+1})
            if (m >= 2) { Gx[m - 2] -= Fx; Gy[m - 2] -= Fy; }   // j = m-2 (F_{j+2})
        }

        // ================= force writes (force = -G) =================
        if (fast) {
            out[3 + 2 * s] = -Gx[0];
            float4* o4 = (float4*)(out + 4 + 2 * s);
            o4[0] = make_float4(-Gy[0], -Gx[1], -Gy[1], -Gx[2]);
            o4[1] = make_float4(-Gy[2], -Gx[3], -Gy[3], -Gx[4]);
            o4[2] = make_float4(-Gy[4], -Gx[5], -Gy[5], -Gx[6]);
            out[16 + 2 * s] = -Gy[6];
            out[17 + 2 * s] = -Gx[7];
            out[18 + 2 * s] = -Gy[7];
        } else {
            #pragma unroll
            for (int j = 0; j < PPT; j++) {
                int p = s + j;
                if (p < N) {
                    bool z = (p < 2);
                    out[3 + 2 * p]     = z ? 0.f : -Gx[j];
                    out[3 + 2 * p + 1] = z ? 0.f : -Gy[j];
                }
            }
        }
    }

    // ---------------- energy reduction ----------------
    float r = rot_e, sv = str_e;
    #pragma unroll
    for (int off = 16; off > 0; off >>= 1) {
        r  += __shfl_down_sync(0xffffffffu, r,  off);
        sv += __shfl_down_sync(0xffffffffu, sv, off);
    }
    const int lane = threadIdx.x & 31;
    const int wid  = threadIdx.x >> 5;
    if (lane == 0) {
        int slot = (blockIdx.x * (TPB / 32) + wid) & 63;
        atomicAdd(&g_rot_acc[slot], 0.5 * (double)r);
        atomicAdd(&g_str_acc[slot], 0.5 * (double)k_stretch * (double)sv);
        __threadfence();
        unsigned tk = atomicAdd(&g_ticket, 1u);
        if (tk == totalWarps - 1u) {
            double R = 0.0, S = 0.0;
            #pragma unroll
            for (int i = 0; i < 64; i++) {
                R += g_rot_acc[i]; g_rot_acc[i] = 0.0;
                S += g_str_acc[i]; g_str_acc[i] = 0.0;
            }
            out[0] = (float)(R + S);
            out[1] = (float)R;
            out[2] = (float)S;
            g_ticket = 0u;
        }
    }
}

extern "C" void kernel_launch(void* const* d_in, const int* in_sizes, int n_in,
                              void* d_out, int out_size) {
    const float2* pos      = (const float2*)d_in[0];
    const float*  th_ss    = (const float*)d_in[1];
    const float*  rest     = (const float*)d_in[2];
    const float*  kstiff   = (const float*)d_in[3];
    const float*  ksoft    = (const float*)d_in[4];
    const float*  kstretch = (const float*)d_in[5];
    const int2*   buckle   = (const int2*)d_in[6];
    float* out = (float*)d_out;

    const int H = in_sizes[1];
    const int N = H + 2;
    const int threads_needed = (N + PPT - 1) / PPT;
    const int blocks = (threads_needed + TPB - 1) / TPB;
    const unsigned totalWarps = (unsigned)blocks * (TPB / 32);

    chain_kernel<<<blocks, TPB>>>(pos, th_ss, rest, kstiff, ksoft, kstretch,
                                  buckle, out, H, totalWarps);
}

// round 16
// speedup vs baseline: 1.4242x; 1.0162x over previous
#include <cuda_runtime.h>

__device__ double g_rot_acc[64];
__device__ double g_str_acc[64];
__device__ unsigned int g_ticket = 0;

#define TPB 128
#define PPT 8
#define NH (PPT + 2)   // 10 hinges per thread: h = s-2 .. s+7
#define NE (PPT + 3)   // 11 edge vectors: vec j = edge (s-2+j)

// Full branch-free atan2 (cephes core), abs err ~1e-7 rad. Fallback path.
__device__ __noinline__ float full_atan2f(float y, float x) {
    float ay = fabsf(y), ax = fabsf(x);
    float mn = fminf(ay, ax), mx = fmaxf(ay, ax);
    bool  big = mn > 0.41421356237f * mx;
    float num = big ? (mn - mx) : mn;
    float den = big ? (mn + mx) : mx;
    float z = __fdividef(num, den);
    float s = z * z;
    float p = fmaf(fmaf(fmaf(fmaf(8.05374449538e-2f, s, -1.38776856032e-1f), s,
                             1.99777106478e-1f), s, -3.33329491539e-1f),
                   s * z, z);
    float r = big ? (0.78539816339744831f + p) : p;
    if (ay > ax) r = 1.57079632679489662f - r;
    if (x < 0.0f) r = 3.14159265358979323f - r;
    return copysignf(r, y);
}

// atan2 specialized for |y| <= 0.414*x (true for this data: edge ~ (1, +-0.03)).
__device__ __forceinline__ float edge_atan2f(float y, float x) {
    if (__builtin_expect(fabsf(y) <= 0.41421356237f * x, 1)) {
        float z = __fdividef(y, x);
        float s = z * z;
        return fmaf(fmaf(fmaf(fmaf(8.05374449538e-2f, s, -1.38776856032e-1f), s,
                              1.99777106478e-1f), s, -3.33329491539e-1f),
                    s * z, z);
    }
    return full_atan2f(y, x);
}

// stiff iff (b==1 && theta > -thss) || (b==-1 && theta < thss)
//      iff (theta with sign flipped by b's sign bit) > -thss   (exact, matches ref)
__device__ __forceinline__ bool stiff_mask(float theta, int b, float thss) {
    float tb = __int_as_float(__float_as_int(theta) ^ (b & 0x80000000));
    return tb > -thss;
}

__global__ void __launch_bounds__(TPB, 6)
chain_kernel(const float2* __restrict__ pos,
             const float*  __restrict__ th_ss,
             const float*  __restrict__ rest,
             const float*  __restrict__ p_kstiff,
             const float*  __restrict__ p_ksoft,
             const float*  __restrict__ p_kstretch,
             const int2*   __restrict__ buckle,
             float*        __restrict__ out,
             int H, unsigned totalWarps)
{
    const int N = H + 2;
    const int t = blockIdx.x * TPB + threadIdx.x;
    const int s = t * PPT;

    const float k_stiff   = __ldg(p_kstiff);
    const float k_soft    = __ldg(p_ksoft);
    const float k_stretch = __ldg(p_kstretch);

    float rot_e = 0.f, str_e = 0.f;   // raw sums: keff*diff^2 and dl^2

    const bool fast = (s >= PPT) && (s + PPT <= H);

    if (s < N) {
        float Ex[NE], Ey[NE];
        float TH[NH];
        int   B0[NH], B1[NH];
        float RL[NE];                  // RL[1..9] real; 0,10 dummies

        // ================= loads (only part that branches) =================
        if (fast) {
            {
                float px[PPT + 4], py[PPT + 4];
                const float4* p4 = (const float4*)(pos + (s - 2));
                #pragma unroll
                for (int i = 0; i < 6; i++) {
                    float4 v = __ldg(&p4[i]);
                    px[2 * i] = v.x; py[2 * i] = v.y;
                    px[2 * i + 1] = v.z; py[2 * i + 1] = v.w;
                }
                #pragma unroll
                for (int j = 0; j < NE; j++) {
                    Ex[j] = px[j + 1] - px[j];
                    Ey[j] = py[j + 1] - py[j];
                }
            }
            {
                float2 c2 = __ldg((const float2*)(th_ss + (s - 2)));
                TH[0] = c2.x; TH[1] = c2.y;
                float4 a = __ldg((const float4*)(th_ss + s));
                float4 b = __ldg((const float4*)(th_ss + s + 4));
                TH[2] = a.x; TH[3] = a.y; TH[4] = a.z; TH[5] = a.w;
                TH[6] = b.x; TH[7] = b.y; TH[8] = b.z; TH[9] = b.w;
            }
            {
                const int4* b4 = (const int4*)(buckle + (s - 2));
                #pragma unroll
                for (int i = 0; i < 5; i++) {
                    int4 v = __ldg(&b4[i]);
                    B0[2 * i]     = v.x; B1[2 * i]     = v.y;
                    B0[2 * i + 1] = v.z; B1[2 * i + 1] = v.w;
                }
            }
            {
                RL[0] = 1.f;
                RL[1] = __ldg(&rest[s - 1]);
                float4 a = __ldg((const float4*)(rest + s));
                float4 b = __ldg((const float4*)(rest + s + 4));
                RL[2] = a.x; RL[3] = a.y; RL[4] = a.z; RL[5] = a.w;
                RL[6] = b.x; RL[7] = b.y; RL[8] = b.z; RL[9] = b.w;
                RL[10] = 1.f;
            }
        } else {
            {
                float px[PPT + 4], py[PPT + 4];
                #pragma unroll
                for (int j = 0; j < PPT + 4; j++) {
                    int g = max(0, min(s - 2 + j, N - 1));
                    float2 v = __ldg(&pos[g]);
                    px[j] = v.x; py[j] = v.y;
                }
                #pragma unroll
                for (int j = 0; j < NE; j++) {
                    int e = s - 2 + j;
                    bool ve = (e >= 0) && (e <= H);
                    Ex[j] = ve ? (px[j + 1] - px[j]) : 1.f;  // dummy (1,0): phi=0, len=1
                    Ey[j] = ve ? (py[j + 1] - py[j]) : 0.f;
                }
            }
            #pragma unroll
            for (int i = 0; i < NH; i++) {
                int h = s - 2 + i;
                bool v = (h >= 0) && (h < H);
                TH[i] = v ? __ldg(&th_ss[h]) : 0.f;
                int2 b = v ? __ldg(&buckle[h]) : make_int2(0, 0);
                B0[i] = b.x; B1[i] = b.y;
            }
            #pragma unroll
            for (int j = 0; j < NE; j++) {
                int e = s - 2 + j;
                RL[j] = ((e >= 0) && (e <= H)) ? __ldg(&rest[e]) : 1.f; // dummy -> dl=0
            }
        }

        // ============ pass A: per-edge absolute angles (11 indep chains) ============
        float phi[NE];
        #pragma unroll
        for (int m = 0; m < NE; m++)
            phi[m] = edge_atan2f(Ey[m], Ex[m]);

        // ============ pass B: hinges -> g, then c_m = g_{m-1} - g_m ============
        float c[NE - 1];   // c[1..9] used
        float gprev = 0.f;
        #pragma unroll
        for (int i = 0; i < NH; i++) {
            float theta = phi[i + 1] - phi[i];
            float th = TH[i];
            bool m0 = stiff_mask(theta, B0[i], th);
            bool m1 = stiff_mask(theta, B1[i], th);
            float keff = (m0 ? k_stiff : k_soft) + (m1 ? k_stiff : k_soft);
            float diff = theta - th;
            float g = keff * diff;
            bool vh = fast || (((s - 2 + i) >= 0) && ((s - 2 + i) < H));
            g = vh ? g : 0.f;
            if (i >= 2) rot_e = fmaf(g, diff, rot_e);    // raw keff*diff^2
            if (i >= 1 && i <= 9) c[i] = gprev - g;
            gprev = g;
        }

        // ============ pass C: combined edge force F_m, scatter to points ============
        // F_m = c_m * perp(E_m)/len^2 + k_str*dl*E_m/len ; G[j] = F_{j+1} - F_{j+2}
        float Gx[PPT], Gy[PPT];
        #pragma unroll
        for (int j = 0; j < PPT; j++) { Gx[j] = 0.f; Gy[j] = 0.f; }

        #pragma unroll
        for (int m = 1; m <= 9; m++) {
            float ex = Ex[m], ey = Ey[m];
            float lensq = fmaf(ex, ex, ey * ey);
            float rsq = rsqrtf(lensq);
            float len = lensq * rsq;
            float dl  = len - RL[m];                     // 0 for dummy edges
            if (m >= 2) str_e = fmaf(dl, dl, str_e);     // raw dl^2
            float fsc = k_stretch * dl * rsq;
            float psc = c[m] * rsq * rsq;
            float Fx = fmaf(fsc, ex, -psc * ey);
            float Fy = fmaf(fsc, ey,  psc * ex);
            if (m <= 8) { Gx[m - 1] += Fx; Gy[m - 1] += Fy; }   // j = m-1 (F_{j+1})
            if (m >= 2) { Gx[m - 2] -= Fx; Gy[m - 2] -= Fy; }   // j = m-2 (F_{j+2})
        }

        // ================= force writes (force = -G) =================
        if (fast) {
            out[3 + 2 * s] = -Gx[0];
            float4* o4 = (float4*)(out + 4 + 2 * s);
            o4[0] = make_float4(-Gy[0], -Gx[1], -Gy[1], -Gx[2]);
            o4[1] = make_float4(-Gy[2], -Gx[3], -Gy[3], -Gx[4]);
            o4[2] = make_float4(-Gy[4], -Gx[5], -Gy[5], -Gx[6]);
            out[16 + 2 * s] = -Gy[6];
            out[17 + 2 * s] = -Gx[7];
            out[18 + 2 * s] = -Gy[7];
        } else {
            #pragma unroll
            for (int j = 0; j < PPT; j++) {
                int p = s + j;
                if (p < N) {
                    bool z = (p < 2);
                    out[3 + 2 * p]     = z ? 0.f : -Gx[j];
                    out[3 + 2 * p + 1] = z ? 0.f : -Gy[j];
                }
            }
        }
    }

    // ---------------- energy reduction ----------------
    float r = rot_e, sv = str_e;
    #pragma unroll
    for (int off = 16; off > 0; off >>= 1) {
        r  += __shfl_down_sync(0xffffffffu, r,  off);
        sv += __shfl_down_sync(0xffffffffu, sv, off);
    }
    const int lane = threadIdx.x & 31;
    const int wid  = threadIdx.x >> 5;
    if (lane == 0) {
        int slot = (blockIdx.x * (TPB / 32) + wid) & 63;
        atomicAdd(&g_rot_acc[slot], 0.5 * (double)r);
        atomicAdd(&g_str_acc[slot], 0.5 * (double)k_stretch * (double)sv);
        __threadfence();
        unsigned tk = atomicAdd(&g_ticket, 1u);
        if (tk == totalWarps - 1u) {
            double R = 0.0, S = 0.0;
            #pragma unroll
            for (int i = 0; i < 64; i++) {
                R += g_rot_acc[i]; g_rot_acc[i] = 0.0;
                S += g_str_acc[i]; g_str_acc[i] = 0.0;
            }
            out[0] = (float)(R + S);
            out[1] = (float)R;
            out[2] = (float)S;
            g_ticket = 0u;
        }
    }
}

extern "C" void kernel_launch(void* const* d_in, const int* in_sizes, int n_in,
                              void* d_out, int out_size) {
    const float2* pos      = (const float2*)d_in[0];
    const float*  th_ss    = (const float*)d_in[1];
    const float*  rest     = (const float*)d_in[2];
    const float*  kstiff   = (const float*)d_in[3];
    const float*  ksoft    = (const float*)d_in[4];
    const float*  kstretch = (const float*)d_in[5];
    const int2*   buckle   = (const int2*)d_in[6];
    float* out = (float*)d_out;

    const int H = in_sizes[1];
    const int N = H + 2;
    const int threads_needed = (N + PPT - 1) / PPT;
    const int blocks = (threads_needed + TPB - 1) / TPB;
    const unsigned totalWarps = (unsigned)blocks * (TPB / 32);

    chain_kernel<<<blocks, TPB>>>(pos, th_ss, rest, kstiff, ksoft, kstretch,
                                  buckle, out, H, totalWarps);
}

// round 17
// speedup vs baseline: 1.4470x; 1.0160x over previous
#include <cuda_runtime.h>

__device__ double g_rot_acc[64];
__device__ double g_str_acc[64];
__device__ unsigned int g_ticket = 0;

#define TPB 128
#define PPT 8
#define NH (PPT + 2)   // 10 hinges per thread: h = s-2 .. s+7
#define NE (PPT + 3)   // 11 edge vectors: vec j = edge (s-2+j)

// Full branch-free atan2 (cephes core), abs err ~1e-7 rad. Fallback path.
__device__ __noinline__ float full_atan2f(float y, float x) {
    float ay = fabsf(y), ax = fabsf(x);
    float mn = fminf(ay, ax), mx = fmaxf(ay, ax);
    bool  big = mn > 0.41421356237f * mx;
    float num = big ? (mn - mx) : mn;
    float den = big ? (mn + mx) : mx;
    float z = __fdividef(num, den);
    float s = z * z;
    float p = fmaf(fmaf(fmaf(fmaf(8.05374449538e-2f, s, -1.38776856032e-1f), s,
                             1.99777106478e-1f), s, -3.33329491539e-1f),
                   s * z, z);
    float r = big ? (0.78539816339744831f + p) : p;
    if (ay > ax) r = 1.57079632679489662f - r;
    if (x < 0.0f) r = 3.14159265358979323f - r;
    return copysignf(r, y);
}

// atan2 specialized for |y| <= 0.414*x (true for this data: edge ~ (1, +-0.03)).
__device__ __forceinline__ float edge_atan2f(float y, float x) {
    if (__builtin_expect(fabsf(y) <= 0.41421356237f * x, 1)) {
        float z = __fdividef(y, x);
        float s = z * z;
        return fmaf(fmaf(fmaf(fmaf(8.05374449538e-2f, s, -1.38776856032e-1f), s,
                              1.99777106478e-1f), s, -3.33329491539e-1f),
                    s * z, z);
    }
    return full_atan2f(y, x);
}

// stiff iff (b==1 && theta > -thss) || (b==-1 && theta < thss)
//      iff (theta with sign flipped by b's sign bit) > -thss   (exact, matches ref)
__device__ __forceinline__ bool stiff_mask(float theta, int b, float thss) {
    float tb = __int_as_float(__float_as_int(theta) ^ (b & 0x80000000));
    return tb > -thss;
}

__global__ void __launch_bounds__(TPB, 6)
chain_kernel(const float2* __restrict__ pos,
             const float*  __restrict__ th_ss,
             const float*  __restrict__ rest,
             const float*  __restrict__ p_kstiff,
             const float*  __restrict__ p_ksoft,
             const float*  __restrict__ p_kstretch,
             const int2*   __restrict__ buckle,
             float*        __restrict__ out,
             int H, unsigned totalWarps)
{
    const int N = H + 2;
    const int t = blockIdx.x * TPB + threadIdx.x;
    const int s = t * PPT;

    const float k_stiff   = __ldg(p_kstiff);
    const float k_soft    = __ldg(p_ksoft);
    const float k_stretch = __ldg(p_kstretch);

    float rot_e = 0.f, str_e = 0.f;   // raw sums: keff*diff^2 and dl^2

    const bool fast = (s >= PPT) && (s + PPT <= H);

    if (s < N) {
        float Ex[NE], Ey[NE];
        float TH[NH];
        int   B0[NH], B1[NH];
        float RL[NE];                  // RL[1..9] real; 0,10 dummies

        // ================= loads (only part that branches) =================
        if (fast) {
            {
                float px[PPT + 4], py[PPT + 4];
                const float4* p4 = (const float4*)(pos + (s - 2));
                #pragma unroll
                for (int i = 0; i < 6; i++) {
                    float4 v = __ldg(&p4[i]);
                    px[2 * i] = v.x; py[2 * i] = v.y;
                    px[2 * i + 1] = v.z; py[2 * i + 1] = v.w;
                }
                #pragma unroll
                for (int j = 0; j < NE; j++) {
                    Ex[j] = px[j + 1] - px[j];
                    Ey[j] = py[j + 1] - py[j];
                }
            }
            {
                float2 c2 = __ldg((const float2*)(th_ss + (s - 2)));
                TH[0] = c2.x; TH[1] = c2.y;
                float4 a = __ldg((const float4*)(th_ss + s));
                float4 b = __ldg((const float4*)(th_ss + s + 4));
                TH[2] = a.x; TH[3] = a.y; TH[4] = a.z; TH[5] = a.w;
                TH[6] = b.x; TH[7] = b.y; TH[8] = b.z; TH[9] = b.w;
            }
            {
                const int4* b4 = (const int4*)(buckle + (s - 2));
                #pragma unroll
                for (int i = 0; i < 5; i++) {
                    int4 v = __ldg(&b4[i]);
                    B0[2 * i]     = v.x; B1[2 * i]     = v.y;
                    B0[2 * i + 1] = v.z; B1[2 * i + 1] = v.w;
                }
            }
            {
                RL[0] = 1.f;
                RL[1] = __ldg(&rest[s - 1]);
                float4 a = __ldg((const float4*)(rest + s));
                float4 b = __ldg((const float4*)(rest + s + 4));
                RL[2] = a.x; RL[3] = a.y; RL[4] = a.z; RL[5] = a.w;
                RL[6] = b.x; RL[7] = b.y; RL[8] = b.z; RL[9] = b.w;
                RL[10] = 1.f;
            }
        } else {
            {
                float px[PPT + 4], py[PPT + 4];
                #pragma unroll
                for (int j = 0; j < PPT + 4; j++) {
                    int g = max(0, min(s - 2 + j, N - 1));
                    float2 v = __ldg(&pos[g]);
                    px[j] = v.x; py[j] = v.y;
                }
                #pragma unroll
                for (int j = 0; j < NE; j++) {
                    int e = s - 2 + j;
                    bool ve = (e >= 0) && (e <= H);
                    Ex[j] = ve ? (px[j + 1] - px[j]) : 1.f;  // dummy (1,0): phi=0, len=1
                    Ey[j] = ve ? (py[j + 1] - py[j]) : 0.f;
                }
            }
            #pragma unroll
            for (int i = 0; i < NH; i++) {
                int h = s - 2 + i;
                bool v = (h >= 0) && (h < H);
                TH[i] = v ? __ldg(&th_ss[h]) : 0.f;
                int2 b = v ? __ldg(&buckle[h]) : make_int2(0, 0);
                B0[i] = b.x; B1[i] = b.y;
            }
            #pragma unroll
            for (int j = 0; j < NE; j++) {
                int e = s - 2 + j;
                RL[j] = ((e >= 0) && (e <= H)) ? __ldg(&rest[e]) : 1.f; // dummy -> dl=0
            }
        }

        // ============ pass A: per-edge absolute angles (11 indep chains) ============
        float phi[NE];
        #pragma unroll
        for (int m = 0; m < NE; m++)
            phi[m] = edge_atan2f(Ey[m], Ex[m]);

        // ============ pass B: hinges -> g, then c_m = g_{m-1} - g_m ============
        float c[NE - 1];   // c[1..9] used
        float gprev = 0.f;
        #pragma unroll
        for (int i = 0; i < NH; i++) {
            float theta = phi[i + 1] - phi[i];
            float th = TH[i];
            bool m0 = stiff_mask(theta, B0[i], th);
            bool m1 = stiff_mask(theta, B1[i], th);
            float keff = (m0 ? k_stiff : k_soft) + (m1 ? k_stiff : k_soft);
            float diff = theta - th;
            float g = keff * diff;
            bool vh = fast || (((s - 2 + i) >= 0) && ((s - 2 + i) < H));
            g = vh ? g : 0.f;
            if (i >= 2) rot_e = fmaf(g, diff, rot_e);    // raw keff*diff^2
            if (i >= 1 && i <= 9) c[i] = gprev - g;
            gprev = g;
        }

        // ============ pass C: combined edge force F_m, scatter to points ============
        // F_m = c_m * perp(E_m)/len^2 + k_str*dl*E_m/len ; G[j] = F_{j+1} - F_{j+2}
        float Gx[PPT], Gy[PPT];
        #pragma unroll
        for (int j = 0; j < PPT; j++) { Gx[j] = 0.f; Gy[j] = 0.f; }

        #pragma unroll
        for (int m = 1; m <= 9; m++) {
            float ex = Ex[m], ey = Ey[m];
            float lensq = fmaf(ex, ex, ey * ey);
            float rsq = rsqrtf(lensq);
            float len = lensq * rsq;
            float dl  = len - RL[m];                     // 0 for dummy edges
            if (m >= 2) str_e = fmaf(dl, dl, str_e);     // raw dl^2
            float fsc = k_stretch * dl * rsq;
            float psc = c[m] * rsq * rsq;
            float Fx = fmaf(fsc, ex, -psc * ey);
            float Fy = fmaf(fsc, ey,  psc * ex);
            if (m <= 8) { Gx[m - 1] += Fx; Gy[m - 1] += Fy; }   // j = m-1 (F_{j+1})
            if (m >= 2) { Gx[m - 2] -= Fx; Gy[m - 2] -= Fy; }   // j = m-2 (F_{j+2})
        }

        // ================= force writes (force = -G) =================
        if (fast) {
            out[3 + 2 * s] = -Gx[0];
            float4* o4 = (float4*)(out + 4 + 2 * s);
            o4[0] = make_float4(-Gy[0], -Gx[1], -Gy[1], -Gx[2]);
            o4[1] = make_float4(-Gy[2], -Gx[3], -Gy[3], -Gx[4]);
            o4[2] = make_float4(-Gy[4], -Gx[5], -Gy[5], -Gx[6]);
            out[16 + 2 * s] = -Gy[6];
            out[17 + 2 * s] = -Gx[7];
            out[18 + 2 * s] = -Gy[7];
        } else {
            #pragma unroll
            for (int j = 0; j < PPT; j++) {
                int p = s + j;
                if (p < N) {
                    bool z = (p < 2);
                    out[3 + 2 * p]     = z ? 0.f : -Gx[j];
                    out[3 + 2 * p + 1] = z ? 0.f : -Gy[j];
                }
            }
        }
    }

    // ---------------- energy reduction ----------------
    float r = rot_e, sv = str_e;
    #pragma unroll
    for (int off = 16; off > 0; off >>= 1) {
        r  += __shfl_down_sync(0xffffffffu, r,  off);
        sv += __shfl_down_sync(0xffffffffu, sv, off);
    }
    const int lane = threadIdx.x & 31;
    const int wid  = threadIdx.x >> 5;
    if (lane == 0) {
        int slot = (blockIdx.x * (TPB / 32) + wid) & 63;
        atomicAdd(&g_rot_acc[slot], 0.5 * (double)r);
        atomicAdd(&g_str_acc[slot], 0.5 * (double)k_stretch * (double)sv);
        __threadfence();
        unsigned tk = atomicAdd(&g_ticket, 1u);
        if (tk == totalWarps - 1u) {
            double R = 0.0, S = 0.0;
            #pragma unroll
            for (int i = 0; i < 64; i++) {
                R += g_rot_acc[i]; g_rot_acc[i] = 0.0;
                S += g_str_acc[i]; g_str_acc[i] = 0.0;
            }
            out[0] = (float)(R + S);
            out[1] = (float)R;
            out[2] = (float)S;
            g_ticket = 0u;
        }
    }
}

extern "C" void kernel_launch(void* const* d_in, const int* in_sizes, int n_in,
                              void* d_out, int out_size) {
    const float2* pos      = (const float2*)d_in[0];
    const float*  th_ss    = (const float*)d_in[1];
    const float*  rest     = (const float*)d_in[2];
    const float*  kstiff   = (const float*)d_in[3];
    const float*  ksoft    = (const float*)d_in[4];
    const float*  kstretch = (const float*)d_in[5];
    const int2*   buckle   = (const int2*)d_in[6];
    float* out = (float*)d_out;

    const int H = in_sizes[1];
    const int N = H + 2;
    const int threads_needed = (N + PPT - 1) / PPT;
    const int blocks = (threads_needed + TPB - 1) / TPB;
    const unsigned totalWarps = (unsigned)blocks * (TPB / 32);

    chain_kernel<<<blocks, TPB>>>(pos, th_ss, rest, kstiff, ksoft, kstretch,
                                  buckle, out, H, totalWarps);
}